// round 8
// baseline (speedup 1.0000x reference)
#include <cuda_runtime.h>
#include <cstdint>

#define WG_EPS 1e-8f
#define TILE 128
#define THREADS 128
#define STAGES 2

struct __align__(16) Stage {
    float l1[3 * TILE];
    float s1[3 * TILE];
    float l2[3 * TILE];
    float s2[3 * TILE];
    float r1[9 * TILE];
    float r2[9 * TILE];
};
#define STAGE_BYTES ((uint32_t)sizeof(Stage))   // 15360

__device__ __forceinline__ uint32_t smem_u32(const void* p) {
    return (uint32_t)__cvta_generic_to_shared(p);
}
__device__ __forceinline__ void mbar_init(uint32_t bar, uint32_t count) {
    asm volatile("mbarrier.init.shared.b64 [%0], %1;" :: "r"(bar), "r"(count) : "memory");
}
__device__ __forceinline__ void mbar_expect_tx(uint32_t bar, uint32_t bytes) {
    asm volatile("mbarrier.arrive.expect_tx.shared.b64 _, [%0], %1;" :: "r"(bar), "r"(bytes) : "memory");
}
__device__ __forceinline__ void mbar_arrive(uint32_t bar) {
    asm volatile("mbarrier.arrive.shared.b64 _, [%0];" :: "r"(bar) : "memory");
}
__device__ __forceinline__ void mbar_wait(uint32_t bar, uint32_t phase) {
    uint32_t done;
    asm volatile("{\n\t.reg .pred p;\n\t"
                 "mbarrier.try_wait.parity.acquire.cta.shared::cta.b64 p, [%1], %2;\n\t"
                 "selp.b32 %0, 1, 0, p;\n\t}"
                 : "=r"(done) : "r"(bar), "r"(phase) : "memory");
    if (!done) {
        asm volatile("{\n\t.reg .pred P1;\n\t"
                     "WL_%=:\n\t"
                     "mbarrier.try_wait.parity.acquire.cta.shared::cta.b64 P1, [%0], %1, 0x989680;\n\t"
                     "@P1 bra.uni WD_%=;\n\t"
                     "bra.uni WL_%=;\n\t"
                     "WD_%=:\n\t}"
                     :: "r"(bar), "r"(phase) : "memory");
    }
}
__device__ __forceinline__ void bulk_copy(uint32_t dst, const float* src, uint32_t bytes, uint32_t bar) {
    asm volatile("cp.async.bulk.shared::cluster.global.mbarrier::complete_tx::bytes [%0], [%1], %2, [%3];"
                 :: "r"(dst), "l"(src), "r"(bytes), "r"(bar) : "memory");
}

__device__ __forceinline__ float wg_compute(
    const float l1[3], const float s1[3], const float r1[9],
    const float l2[3], const float s2[3], const float r2[9])
{
    float d0 = l1[0] - l2[0], d1 = l1[1] - l2[1], d2 = l1[2] - l2[2];
    float loc_diff2 = d0 * d0 + d1 * d1 + d2 * d2;

    float cov2[3][3];
#pragma unroll
    for (int i = 0; i < 3; i++) {
#pragma unroll
        for (int k = i; k < 3; k++) {
            float v = r2[3 * i + 0] * s2[0] * r2[3 * k + 0]
                    + r2[3 * i + 1] * s2[1] * r2[3 * k + 1]
                    + r2[3 * i + 2] * s2[2] * r2[3 * k + 2];
            cov2[i][k] = v;
            cov2[k][i] = v;
        }
    }
    float tr_cov2 = cov2[0][0] + cov2[1][1] + cov2[2][2];

    float T[3][3];
#pragma unroll
    for (int j = 0; j < 3; j++)
#pragma unroll
        for (int l = 0; l < 3; l++)
            T[j][l] = cov2[j][0] * r1[0 * 3 + l]
                    + cov2[j][1] * r1[1 * 3 + l]
                    + cov2[j][2] * r1[2 * 3 + l];

    float M[3][3];
#pragma unroll
    for (int i = 0; i < 3; i++)
#pragma unroll
        for (int l = 0; l < 3; l++)
            M[i][l] = r1[0 * 3 + i] * T[0][l]
                    + r1[1 * 3 + i] * T[1][l]
                    + r1[2 * 3 + i] * T[2][l];

    float q0 = sqrtf(s1[0]), q1 = sqrtf(s1[1]), q2 = sqrtf(s1[2]);
    float a00 = s1[0] * M[0][0] + WG_EPS;
    float a11 = s1[1] * M[1][1] + WG_EPS;
    float a22 = s1[2] * M[2][2] + WG_EPS;
    float a01 = q0 * q1 * 0.5f * (M[0][1] + M[1][0]);
    float a02 = q0 * q2 * 0.5f * (M[0][2] + M[2][0]);
    float a12 = q1 * q2 * 0.5f * (M[1][2] + M[2][1]);

    float q  = (a00 + a11 + a22) * (1.0f / 3.0f);
    float p1 = a01 * a01 + a02 * a02 + a12 * a12;
    float m0 = a00 - q, m1 = a11 - q, m2 = a22 - q;
    float p2 = m0 * m0 + m1 * m1 + m2 * m2 + 2.0f * p1;

    float sum_sqrt;
    if (p2 <= 1e-24f) {
        sum_sqrt = 3.0f * sqrtf(fmaxf(q, WG_EPS));
    } else {
        float p  = sqrtf(p2 * (1.0f / 6.0f));
        float ip = 1.0f / p;
        float b00 = m0 * ip, b11 = m1 * ip, b22 = m2 * ip;
        float b01 = a01 * ip, b02 = a02 * ip, b12 = a12 * ip;
        float detB = b00 * (b11 * b22 - b12 * b12)
                   - b01 * (b01 * b22 - b12 * b02)
                   + b02 * (b01 * b12 - b11 * b02);
        float r = fminf(fmaxf(0.5f * detB, -1.0f), 1.0f);
        float phi = acosf(r) * (1.0f / 3.0f);
        float tp = 2.0f * p;
        float e1 = q + tp * cosf(phi);
        float e3 = q + tp * cosf(phi + 2.0943951023931953f);
        float e2 = 3.0f * q - e1 - e3;
        sum_sqrt = sqrtf(fmaxf(e1, WG_EPS))
                 + sqrtf(fmaxf(e2, WG_EPS))
                 + sqrtf(fmaxf(e3, WG_EPS));
    }

    float cov_w = (s1[0] + s1[1] + s1[2]) + tr_cov2 - 2.0f * sum_sqrt;
    cov_w = fmaxf(cov_w, 0.0f);
    return sqrtf(fmaxf(loc_diff2 + cov_w, WG_EPS));
}

__global__ __launch_bounds__(THREADS) void wasserstein_gaussian_kernel(
    const float* __restrict__ loc1,
    const float* __restrict__ scale1,
    const float* __restrict__ rot1,
    const float* __restrict__ loc2,
    const float* __restrict__ scale2,
    const float* __restrict__ rot2,
    float* __restrict__ out,
    int B, int ntiles)
{
    __shared__ Stage stg[STAGES];
    __shared__ __align__(8) uint64_t bar_full[STAGES];
    __shared__ __align__(8) uint64_t bar_empty[STAGES];

    const int tid = threadIdx.x;

    if (tid == 0) {
#pragma unroll
        for (int s = 0; s < STAGES; s++) {
            mbar_init(smem_u32(&bar_full[s]), 1);
            mbar_init(smem_u32(&bar_empty[s]), THREADS);
        }
    }
    __syncthreads();

    // ---- prologue: fill both stages ----
    if (tid == 0) {
        int issued = 0;
        for (int t = blockIdx.x; t < ntiles && issued < STAGES; t += gridDim.x, issued++) {
            uint32_t fb = smem_u32(&bar_full[issued]);
            mbar_expect_tx(fb, STAGE_BYTES);
            Stage* st = &stg[issued];
            bulk_copy(smem_u32(st->l1), loc1   + 3 * TILE * t, 3 * TILE * 4, fb);
            bulk_copy(smem_u32(st->s1), scale1 + 3 * TILE * t, 3 * TILE * 4, fb);
            bulk_copy(smem_u32(st->l2), loc2   + 3 * TILE * t, 3 * TILE * 4, fb);
            bulk_copy(smem_u32(st->s2), scale2 + 3 * TILE * t, 3 * TILE * 4, fb);
            bulk_copy(smem_u32(st->r1), rot1   + 9 * TILE * t, 9 * TILE * 4, fb);
            bulk_copy(smem_u32(st->r2), rot2   + 9 * TILE * t, 9 * TILE * 4, fb);
        }
    }

    // ---- main pipeline ----
    int i = 0;
    for (int t = blockIdx.x; t < ntiles; t += gridDim.x, i++) {
        int s = i & (STAGES - 1);
        uint32_t ph = (i / STAGES) & 1;
        mbar_wait(smem_u32(&bar_full[s]), ph);

        Stage* st = &stg[s];
        float l1v[3], l2v[3], s1v[3], s2v[3], r1v[9], r2v[9];
#pragma unroll
        for (int k = 0; k < 3; k++) {
            l1v[k] = st->l1[3 * tid + k];
            l2v[k] = st->l2[3 * tid + k];
            s1v[k] = fmaxf(st->s1[3 * tid + k], WG_EPS);
            s2v[k] = fmaxf(st->s2[3 * tid + k], WG_EPS);
        }
#pragma unroll
        for (int k = 0; k < 9; k++) {
            r1v[k] = st->r1[9 * tid + k];
            r2v[k] = st->r2[9 * tid + k];
        }

        out[t * TILE + tid] = wg_compute(l1v, s1v, r1v, l2v, s2v, r2v);

        mbar_arrive(smem_u32(&bar_empty[s]));

        if (tid == 0) {
            int tn = t + STAGES * gridDim.x;
            if (tn < ntiles) {
                // wait until all threads consumed round i/STAGES of stage s
                mbar_wait(smem_u32(&bar_empty[s]), ph);
                uint32_t fb = smem_u32(&bar_full[s]);
                mbar_expect_tx(fb, STAGE_BYTES);
                bulk_copy(smem_u32(st->l1), loc1   + 3 * TILE * tn, 3 * TILE * 4, fb);
                bulk_copy(smem_u32(st->s1), scale1 + 3 * TILE * tn, 3 * TILE * 4, fb);
                bulk_copy(smem_u32(st->l2), loc2   + 3 * TILE * tn, 3 * TILE * 4, fb);
                bulk_copy(smem_u32(st->s2), scale2 + 3 * TILE * tn, 3 * TILE * 4, fb);
                bulk_copy(smem_u32(st->r1), rot1   + 9 * TILE * tn, 9 * TILE * 4, fb);
                bulk_copy(smem_u32(st->r2), rot2   + 9 * TILE * tn, 9 * TILE * 4, fb);
            }
        }
    }

    // ---- tail (B not a multiple of TILE): direct strided loads, CTA 0 ----
    int done = ntiles * TILE;
    if (blockIdx.x == 0) {
        int b = done + tid;
        if (b < B) {
            float l1v[3], l2v[3], s1v[3], s2v[3], r1v[9], r2v[9];
#pragma unroll
            for (int k = 0; k < 3; k++) {
                l1v[k] = loc1[3 * b + k];
                l2v[k] = loc2[3 * b + k];
                s1v[k] = fmaxf(scale1[3 * b + k], WG_EPS);
                s2v[k] = fmaxf(scale2[3 * b + k], WG_EPS);
            }
#pragma unroll
            for (int k = 0; k < 9; k++) {
                r1v[k] = rot1[9 * b + k];
                r2v[k] = rot2[9 * b + k];
            }
            out[b] = wg_compute(l1v, s1v, r1v, l2v, s2v, r2v);
        }
    }
}

extern "C" void kernel_launch(void* const* d_in, const int* in_sizes, int n_in,
                              void* d_out, int out_size)
{
    const float* loc1   = (const float*)d_in[0];
    const float* scale1 = (const float*)d_in[1];
    const float* rot1   = (const float*)d_in[2];
    const float* loc2   = (const float*)d_in[3];
    const float* scale2 = (const float*)d_in[4];
    const float* rot2   = (const float*)d_in[5];
    float* out = (float*)d_out;

    int B = in_sizes[0] / 3;
    int ntiles = B / TILE;                 // full tiles through the pipeline
    int blocks = 148 * 7;                  // persistent: 7 CTAs/SM (30KB smem each)
    if (blocks > ntiles) blocks = (ntiles > 0) ? ntiles : 1;

    wasserstein_gaussian_kernel<<<blocks, THREADS>>>(
        loc1, scale1, rot1, loc2, scale2, rot2, out, B, ntiles);
}

// round 9
// speedup vs baseline: 1.5765x; 1.5765x over previous
#include <cuda_runtime.h>
#include <cstdint>

#define WG_EPS 1e-8f
#define TILE 256
#define THREADS 256
#define STAGES 2

// One stage = all six arrays for TILE Gaussians, each sub-array 16B aligned.
struct __align__(16) Stage {
    float l1[3 * TILE];   // 192 float4
    float s1[3 * TILE];
    float l2[3 * TILE];
    float s2[3 * TILE];
    float r1[9 * TILE];   // 576 float4
    float r2[9 * TILE];
};
// sizeof(Stage) = 30720 B; 2 stages = 61440 B dynamic SMEM -> 3 CTAs/SM.

__device__ __forceinline__ uint32_t smem_u32(const void* p) {
    return (uint32_t)__cvta_generic_to_shared(p);
}
__device__ __forceinline__ void cp16(void* dst_smem, const void* src) {
    asm volatile("cp.async.cg.shared.global [%0], [%1], 16;"
                 :: "r"(smem_u32(dst_smem)), "l"(src) : "memory");
}
__device__ __forceinline__ void cp_commit() {
    asm volatile("cp.async.commit_group;" ::: "memory");
}
template <int N>
__device__ __forceinline__ void cp_wait() {
    asm volatile("cp.async.wait_group %0;" :: "n"(N) : "memory");
}

__device__ __forceinline__ void fill_stage(
    Stage* st, int t, int tid,
    const float* loc1, const float* scale1, const float* rot1,
    const float* loc2, const float* scale2, const float* rot2)
{
    const float4* pl1 = (const float4*)(loc1   + 3 * TILE * t);
    const float4* ps1 = (const float4*)(scale1 + 3 * TILE * t);
    const float4* pl2 = (const float4*)(loc2   + 3 * TILE * t);
    const float4* ps2 = (const float4*)(scale2 + 3 * TILE * t);
    const float4* pr1 = (const float4*)(rot1   + 9 * TILE * t);
    const float4* pr2 = (const float4*)(rot2   + 9 * TILE * t);

    if (tid < 192) {   // 3*TILE/4 = 192 float4 per small array
        cp16((float4*)st->l1 + tid, pl1 + tid);
        cp16((float4*)st->s1 + tid, ps1 + tid);
        cp16((float4*)st->l2 + tid, pl2 + tid);
        cp16((float4*)st->s2 + tid, ps2 + tid);
    }
    // 9*TILE/4 = 576 float4 per rot array
    cp16((float4*)st->r1 + tid,       pr1 + tid);
    cp16((float4*)st->r1 + tid + 256, pr1 + tid + 256);
    cp16((float4*)st->r2 + tid,       pr2 + tid);
    cp16((float4*)st->r2 + tid + 256, pr2 + tid + 256);
    if (tid < 64) {
        cp16((float4*)st->r1 + tid + 512, pr1 + tid + 512);
        cp16((float4*)st->r2 + tid + 512, pr2 + tid + 512);
    }
}

__device__ __forceinline__ float wg_compute(
    const float l1[3], const float s1[3], const float r1[9],
    const float l2[3], const float s2[3], const float r2[9])
{
    float d0 = l1[0] - l2[0], d1 = l1[1] - l2[1], d2 = l1[2] - l2[2];
    float loc_diff2 = d0 * d0 + d1 * d1 + d2 * d2;

    float cov2[3][3];
#pragma unroll
    for (int i = 0; i < 3; i++) {
#pragma unroll
        for (int k = i; k < 3; k++) {
            float v = r2[3 * i + 0] * s2[0] * r2[3 * k + 0]
                    + r2[3 * i + 1] * s2[1] * r2[3 * k + 1]
                    + r2[3 * i + 2] * s2[2] * r2[3 * k + 2];
            cov2[i][k] = v;
            cov2[k][i] = v;
        }
    }
    float tr_cov2 = cov2[0][0] + cov2[1][1] + cov2[2][2];

    float T[3][3];
#pragma unroll
    for (int j = 0; j < 3; j++)
#pragma unroll
        for (int l = 0; l < 3; l++)
            T[j][l] = cov2[j][0] * r1[0 * 3 + l]
                    + cov2[j][1] * r1[1 * 3 + l]
                    + cov2[j][2] * r1[2 * 3 + l];

    float M[3][3];
#pragma unroll
    for (int i = 0; i < 3; i++)
#pragma unroll
        for (int l = 0; l < 3; l++)
            M[i][l] = r1[0 * 3 + i] * T[0][l]
                    + r1[1 * 3 + i] * T[1][l]
                    + r1[2 * 3 + i] * T[2][l];

    float q0 = sqrtf(s1[0]), q1 = sqrtf(s1[1]), q2 = sqrtf(s1[2]);
    float a00 = s1[0] * M[0][0] + WG_EPS;
    float a11 = s1[1] * M[1][1] + WG_EPS;
    float a22 = s1[2] * M[2][2] + WG_EPS;
    float a01 = q0 * q1 * 0.5f * (M[0][1] + M[1][0]);
    float a02 = q0 * q2 * 0.5f * (M[0][2] + M[2][0]);
    float a12 = q1 * q2 * 0.5f * (M[1][2] + M[2][1]);

    float q  = (a00 + a11 + a22) * (1.0f / 3.0f);
    float p1 = a01 * a01 + a02 * a02 + a12 * a12;
    float m0 = a00 - q, m1 = a11 - q, m2 = a22 - q;
    float p2 = m0 * m0 + m1 * m1 + m2 * m2 + 2.0f * p1;

    float sum_sqrt;
    if (p2 <= 1e-24f) {
        sum_sqrt = 3.0f * sqrtf(fmaxf(q, WG_EPS));
    } else {
        float p  = sqrtf(p2 * (1.0f / 6.0f));
        float ip = 1.0f / p;
        float b00 = m0 * ip, b11 = m1 * ip, b22 = m2 * ip;
        float b01 = a01 * ip, b02 = a02 * ip, b12 = a12 * ip;
        float detB = b00 * (b11 * b22 - b12 * b12)
                   - b01 * (b01 * b22 - b12 * b02)
                   + b02 * (b01 * b12 - b11 * b02);
        float r = fminf(fmaxf(0.5f * detB, -1.0f), 1.0f);
        float phi = acosf(r) * (1.0f / 3.0f);
        float tp = 2.0f * p;
        float e1 = q + tp * cosf(phi);
        float e3 = q + tp * cosf(phi + 2.0943951023931953f);
        float e2 = 3.0f * q - e1 - e3;
        sum_sqrt = sqrtf(fmaxf(e1, WG_EPS))
                 + sqrtf(fmaxf(e2, WG_EPS))
                 + sqrtf(fmaxf(e3, WG_EPS));
    }

    float cov_w = (s1[0] + s1[1] + s1[2]) + tr_cov2 - 2.0f * sum_sqrt;
    cov_w = fmaxf(cov_w, 0.0f);
    return sqrtf(fmaxf(loc_diff2 + cov_w, WG_EPS));
}

__global__ __launch_bounds__(THREADS) void wasserstein_gaussian_kernel(
    const float* __restrict__ loc1,
    const float* __restrict__ scale1,
    const float* __restrict__ rot1,
    const float* __restrict__ loc2,
    const float* __restrict__ scale2,
    const float* __restrict__ rot2,
    float* __restrict__ out,
    int B, int ntiles)
{
    extern __shared__ __align__(16) char smem_raw[];
    Stage* stg = (Stage*)smem_raw;

    const int tid = threadIdx.x;

    // ---- prologue: issue copies for the first STAGES tiles ----
#pragma unroll
    for (int k = 0; k < STAGES; k++) {
        int t = blockIdx.x + k * gridDim.x;
        if (t < ntiles)
            fill_stage(&stg[k], t, tid, loc1, scale1, rot1, loc2, scale2, rot2);
        cp_commit();   // every thread commits a group each stage (may be empty)
    }

    // ---- main pipeline ----
    int i = 0;
    for (int t = blockIdx.x; t < ntiles; t += gridDim.x, i++) {
        int s = i & (STAGES - 1);
        cp_wait<STAGES - 1>();   // oldest group (this stage) has landed
        __syncthreads();         // ...for ALL threads

        Stage* st = &stg[s];
        float l1v[3], l2v[3], s1v[3], s2v[3], r1v[9], r2v[9];
#pragma unroll
        for (int k = 0; k < 3; k++) {
            l1v[k] = st->l1[3 * tid + k];
            l2v[k] = st->l2[3 * tid + k];
            s1v[k] = fmaxf(st->s1[3 * tid + k], WG_EPS);
            s2v[k] = fmaxf(st->s2[3 * tid + k], WG_EPS);
        }
#pragma unroll
        for (int k = 0; k < 9; k++) {
            r1v[k] = st->r1[9 * tid + k];   // stride 9: bank-conflict-free
            r2v[k] = st->r2[9 * tid + k];
        }

        out[t * TILE + tid] = wg_compute(l1v, s1v, r1v, l2v, s2v, r2v);

        __syncthreads();         // whole stage consumed before refill

        int tn = t + STAGES * gridDim.x;
        if (tn < ntiles)
            fill_stage(st, tn, tid, loc1, scale1, rot1, loc2, scale2, rot2);
        cp_commit();
    }

    // ---- tail (B % TILE != 0): CTA 0 handles leftovers with direct loads ----
    if (blockIdx.x == 0) {
        for (int b = ntiles * TILE + tid; b < B; b += THREADS) {
            float l1v[3], l2v[3], s1v[3], s2v[3], r1v[9], r2v[9];
#pragma unroll
            for (int k = 0; k < 3; k++) {
                l1v[k] = loc1[3 * b + k];
                l2v[k] = loc2[3 * b + k];
                s1v[k] = fmaxf(scale1[3 * b + k], WG_EPS);
                s2v[k] = fmaxf(scale2[3 * b + k], WG_EPS);
            }
#pragma unroll
            for (int k = 0; k < 9; k++) {
                r1v[k] = rot1[9 * b + k];
                r2v[k] = rot2[9 * b + k];
            }
            out[b] = wg_compute(l1v, s1v, r1v, l2v, s2v, r2v);
        }
    }
}

extern "C" void kernel_launch(void* const* d_in, const int* in_sizes, int n_in,
                              void* d_out, int out_size)
{
    const float* loc1   = (const float*)d_in[0];
    const float* scale1 = (const float*)d_in[1];
    const float* rot1   = (const float*)d_in[2];
    const float* loc2   = (const float*)d_in[3];
    const float* scale2 = (const float*)d_in[4];
    const float* rot2   = (const float*)d_in[5];
    float* out = (float*)d_out;

    int B = in_sizes[0] / 3;
    int ntiles = B / TILE;

    int smem_bytes = STAGES * (int)sizeof(Stage);  // 61440
    cudaFuncSetAttribute(wasserstein_gaussian_kernel,
                         cudaFuncAttributeMaxDynamicSharedMemorySize, smem_bytes);

    int blocks = 148 * 3;                 // persistent: 3 CTAs/SM at 60KB smem
    if (blocks > ntiles) blocks = (ntiles > 0) ? ntiles : 1;

    wasserstein_gaussian_kernel<<<blocks, THREADS, smem_bytes>>>(
        loc1, scale1, rot1, loc2, scale2, rot2, out, B, ntiles);
}